// round 11
// baseline (speedup 1.0000x reference)
#include <cuda_runtime.h>
#include <math.h>

#define B 32
#define T 512
#define U 1024
#define E 1024
#define DIN 256
#define G4 4096        // 4*U
#define NSPL_IND 10    // independent z chunks (2 inputs + 8 h), k=128 each
#define NSPL_CTX 16    // context z chunks, k=64 each
#define NSPL (NSPL_IND + NSPL_CTX)
#define GRID 296       // 148 SMs x 2 resident blocks
#define NT 512

// ---------------- scratch (device globals: no allocations allowed) ----------
__device__ float g_qpart[16 * B * U];
__device__ float g_query[B * U];
__device__ float g_logits[B * T];
__device__ float g_attn[B * T];
__device__ float g_ctxpart[16 * B * E];
__device__ float g_context[B * E];
__device__ float g_zpart[NSPL * B * G4];
__device__ unsigned int g_count = 0;           // barrier counter (self-resets)
__device__ unsigned int g_gen = 0;             // barrier generation (monotonic)
__device__ unsigned int g_tick[4] = {0,0,0,0}; // work-steal tickets (self-reset)

// ---------------- helpers ----------------------------------------------------
__device__ __forceinline__ unsigned long long pack2(float a, float b) {
    unsigned long long r;
    asm("mov.b64 %0, {%1, %2};" : "=l"(r) : "r"(__float_as_uint(a)), "r"(__float_as_uint(b)));
    return r;
}
__device__ __forceinline__ void unpack2(unsigned long long v, float& a, float& b) {
    unsigned int lo, hi;
    asm("mov.b64 {%0, %1}, %2;" : "=r"(lo), "=r"(hi) : "l"(v));
    a = __uint_as_float(lo); b = __uint_as_float(hi);
}
__device__ __forceinline__ unsigned long long fma2(unsigned long long x,
                                                   unsigned long long y,
                                                   unsigned long long a) {
    unsigned long long d;
    asm("fma.rn.f32x2 %0, %1, %2, %3;" : "=l"(d) : "l"(x), "l"(y), "l"(a));
    return d;
}
__device__ __forceinline__ float tanh_hw(float x) {
    float y;
    asm("tanh.approx.f32 %0, %1;" : "=f"(y) : "f"(x));
    return y;
}
__device__ __forceinline__ float sigmoid_acc(float x) {
    return 1.0f / (1.0f + expf(-x));
}
__device__ __forceinline__ float4 ldcs4(const float4* p) {
    float4 v;
    asm("ld.global.cs.v4.f32 {%0,%1,%2,%3}, [%4];"
        : "=f"(v.x), "=f"(v.y), "=f"(v.z), "=f"(v.w) : "l"(p));
    return v;
}

// Grid-wide barrier: counter + monotonic generation (replay-safe).
__device__ __forceinline__ void grid_barrier() {
    __syncthreads();
    if (threadIdx.x == 0) {
        __threadfence();
        unsigned int gen = atomicAdd(&g_gen, 0u);
        unsigned int arrived = atomicAdd(&g_count, 1u) + 1u;
        if (arrived == GRID) {
            g_count = 0;
            __threadfence();
            atomicAdd(&g_gen, 1u);
        } else {
            while (atomicAdd(&g_gen, 0u) == gen) { __nanosleep(64); }
        }
        __threadfence();
    }
    __syncthreads();
}

// ---------------- the whole cell: stealing in heavy phases --------------------
__global__ void __launch_bounds__(NT, 2) mono_cell(
    const float* __restrict__ inputs, const float* __restrict__ h,
    const float* __restrict__ c, const float* __restrict__ se,
    const float* __restrict__ es, const float* __restrict__ Wa,
    const float* __restrict__ Wa_b, const float* __restrict__ va_w,
    const float* __restrict__ va_b, const float* __restrict__ Wk,
    const float* __restrict__ Wr, const float* __restrict__ bias,
    float* __restrict__ out)
{
    __shared__ __align__(16) float pool[128 * 36];   // 18.4KB, reused per phase
    __shared__ unsigned int s_tile;
    const int tid = threadIdx.x;
    const int bx = blockIdx.x;
    const int gtid = bx * NT + tid;

    // ===== P1 (tick 0): 448 tiles = 128 query + 320 independent-z =============
    for (;;) {
        __syncthreads();
        if (tid == 0) s_tile = atomicAdd(&g_tick[0], 1u);
        __syncthreads();
        const unsigned int tile = s_tile;
        if (tile >= 448u) break;

        if (tile < 128u) {
            // query partial: u-tile(8 of 128) x kb(16 of k=64); bh covers 8 b.
            const int ut = tile >> 4, kb = tile & 15;
            const int k0 = kb * 64;
            const int u = ut * 128 + (tid & 127);
            const int bh = tid >> 7;

            for (int idx = tid; idx < 32 * 64; idx += NT) {
                int b = idx >> 6, k = idx & 63;
                pool[k * 36 + b] = h[b * U + k0 + k];
            }
            __syncthreads();

            unsigned long long acc[4];
#pragma unroll
            for (int p = 0; p < 4; p++) acc[p] = 0ull;
            const float* wcol = Wa + (size_t)k0 * U + u;
#pragma unroll 8
            for (int k = 0; k < 64; k++) {
                float w = wcol[(size_t)k * U];
                unsigned long long ww = pack2(w, w);
                const unsigned long long* xp =
                    reinterpret_cast<const unsigned long long*>(&pool[k * 36]) + bh * 4;
#pragma unroll
                for (int p = 0; p < 4; p++) acc[p] = fma2(xp[p], ww, acc[p]);
            }
            float* outp = g_qpart + (size_t)kb * (B * U);
#pragma unroll
            for (int p = 0; p < 4; p++) {
                float a, b2; unpack2(acc[p], a, b2);
                outp[(bh * 8 + 2 * p) * U + u] = a;
                outp[(bh * 8 + 2 * p + 1) * U + u] = b2;
            }
        } else {
            // independent z: kb(10 of k=128) x jt(32 of j=128)
            const unsigned int zi = tile - 128u;
            const int kb = zi >> 5, jt = zi & 31;
            const int j = jt * 128 + (tid & 127);
            const int bh = tid >> 7;

            const float* xsrc; int x_ld, xk0;
            const float* W;    int wk0;
            if (kb < 2) { xsrc = inputs; x_ld = DIN; xk0 = kb * 128;       W = Wk; wk0 = kb * 128; }
            else        { xsrc = h;      x_ld = U;   xk0 = (kb - 2) * 128; W = Wr; wk0 = (kb - 2) * 128; }

            for (int idx = tid; idx < 32 * 128; idx += NT) {
                int b = idx >> 7, kk = idx & 127;
                pool[kk * 36 + b] = xsrc[(size_t)b * x_ld + xk0 + kk];
            }
            __syncthreads();

            unsigned long long acc[4];
#pragma unroll
            for (int p = 0; p < 4; p++) acc[p] = 0ull;
            const float* wcol = W + (size_t)wk0 * G4 + j;
#pragma unroll 8
            for (int kk = 0; kk < 128; kk++) {
                float w = wcol[(size_t)kk * G4];
                unsigned long long ww = pack2(w, w);
                const unsigned long long* xp =
                    reinterpret_cast<const unsigned long long*>(&pool[kk * 36]) + bh * 4;
#pragma unroll
                for (int p = 0; p < 4; p++) acc[p] = fma2(xp[p], ww, acc[p]);
            }
            float* outp = g_zpart + (size_t)kb * (B * G4);
#pragma unroll
            for (int p = 0; p < 4; p++) {
                float a, b2; unpack2(acc[p], a, b2);
                outp[(size_t)(bh * 8 + 2 * p) * G4 + j] = a;
                outp[(size_t)(bh * 8 + 2 * p + 1) * G4 + j] = b2;
            }
        }
    }
    grid_barrier();

    // ===== P1b: reduce query partials + bias; reset tick0 =====================
    if (bx == 0 && tid == 0) g_tick[0] = 0;
    if (gtid < B * U) {
        float s = Wa_b[gtid & (U - 1)];
#pragma unroll
        for (int kb = 0; kb < 16; kb++) s += g_qpart[kb * (B * U) + gtid];
        g_query[gtid] = s;
    }
    grid_barrier();

    // ===== P2 (tick 1): scores; 1024 tiles = b(32) x sl(32 of 16 rows) ========
    {
        // va cached once per block at pool+1024
        for (int i4 = tid; i4 < 256; i4 += NT)
            reinterpret_cast<float4*>(pool + 1024)[i4] =
                reinterpret_cast<const float4*>(va_w)[i4];
        int cur_b = -1;
        const float vb = va_b[0];
        const int lane = tid & 31;
        for (;;) {
            __syncthreads();
            if (tid == 0) s_tile = atomicAdd(&g_tick[1], 1u);
            __syncthreads();
            const unsigned int tile = s_tile;
            if (tile >= 1024u) break;
            const int b = tile >> 5, sl = tile & 31;

            if (b != cur_b) {
                for (int i4 = tid; i4 < 256; i4 += NT)
                    reinterpret_cast<float4*>(pool)[i4] =
                        reinterpret_cast<const float4*>(g_query + b * U)[i4];
                __syncthreads();
                cur_b = b;
            }

            const float4* qs = reinterpret_cast<const float4*>(pool);
            const float4* vs = reinterpret_cast<const float4*>(pool + 1024);
            const int r = sl * 16 + (tid >> 5);    // one row per warp
            const float4* erow = reinterpret_cast<const float4*>(es)
                               + (size_t)(b * T + r) * 256;
            float4 e[8];
#pragma unroll
            for (int i = 0; i < 8; i++) e[i] = ldcs4(&erow[lane + i * 32]);
            float s = 0.f;
#pragma unroll
            for (int i = 0; i < 8; i++) {
                int u4 = lane + i * 32;
                float4 q4 = qs[u4];
                float4 v4 = vs[u4];
                s += tanh_hw(q4.x + e[i].x) * v4.x;
                s += tanh_hw(q4.y + e[i].y) * v4.y;
                s += tanh_hw(q4.z + e[i].z) * v4.z;
                s += tanh_hw(q4.w + e[i].w) * v4.w;
            }
#pragma unroll
            for (int o = 16; o; o >>= 1) s += __shfl_xor_sync(0xffffffffu, s, o);
            if (lane == 0) g_logits[b * T + r] = s + vb;
        }
    }
    grid_barrier();

    // ===== P3: softmax per batch (32 blocks); reset tick1 =====================
    if (bx == 0 && tid == 0) g_tick[1] = 0;
    if (bx < 32) {
        float* red = pool;
        const int b = bx;
        const int lane = tid & 31, wid = tid >> 5;

        float l = g_logits[b * T + tid];
        float m = l;
#pragma unroll
        for (int o = 16; o; o >>= 1) m = fmaxf(m, __shfl_xor_sync(0xffffffffu, m, o));
        if (lane == 0) red[wid] = m;
        __syncthreads();
        if (tid < 32) {
            float v = red[tid & 15];
#pragma unroll
            for (int o = 8; o; o >>= 1) v = fmaxf(v, __shfl_xor_sync(0xffffffffu, v, o));
            if (tid == 0) red[16] = v;
        }
        __syncthreads();
        float p = __expf(l - red[16]);
        float sum = p;
#pragma unroll
        for (int o = 16; o; o >>= 1) sum += __shfl_xor_sync(0xffffffffu, sum, o);
        if (lane == 0) red[wid] = sum;
        __syncthreads();
        if (tid < 32) {
            float v = (tid < 16) ? red[tid] : 0.f;
#pragma unroll
            for (int o = 8; o; o >>= 1) v += __shfl_xor_sync(0xffffffffu, v, o);
            if (tid == 0) red[17] = v;
        }
        __syncthreads();
        g_attn[b * T + tid] = p / red[17];
    }
    grid_barrier();

    // ===== P4 (tick 2): context partials; 1024 tiles = b(32)xpp(16)xhalf(2) ===
    for (;;) {
        __syncthreads();
        if (tid == 0) s_tile = atomicAdd(&g_tick[2], 1u);
        __syncthreads();
        const unsigned int tile = s_tile;
        if (tile >= 1024u) break;
        const int b = tile >> 5, pp = (tile >> 1) & 15, half = tile & 1;
        const int t0 = pp * 32;

        if (tid < 32) pool[2048 + tid] = g_attn[b * T + t0 + tid];
        __syncthreads();

        const int tsub = tid >> 7, e4i = tid & 127;
        const int e4 = half * 128 + e4i;
        const float* ap = pool + 2048 + tsub * 8;
        const float4* se4 = reinterpret_cast<const float4*>(se)
                          + ((size_t)(b * T + t0 + tsub * 8)) * 256 + e4;
        float4 acc = make_float4(0.f, 0.f, 0.f, 0.f);
#pragma unroll
        for (int i = 0; i < 8; i++) {
            float pw = ap[i];
            float4 v = ldcs4(&se4[(size_t)i * 256]);
            acc.x += pw * v.x; acc.y += pw * v.y; acc.z += pw * v.z; acc.w += pw * v.w;
        }
        float4* pool4 = reinterpret_cast<float4*>(pool);
        pool4[tsub * 128 + e4i] = acc;
        __syncthreads();
        if (tid < 128) {
            float4 r0 = pool4[e4i], r1 = pool4[128 + e4i];
            float4 r2 = pool4[256 + e4i], r3 = pool4[384 + e4i];
            float4 r;
            r.x = (r0.x + r1.x) + (r2.x + r3.x);
            r.y = (r0.y + r1.y) + (r2.y + r3.y);
            r.z = (r0.z + r1.z) + (r2.z + r3.z);
            r.w = (r0.w + r1.w) + (r2.w + r3.w);
            reinterpret_cast<float4*>(g_ctxpart)[(size_t)(pp * B + b) * 256 + e4] = r;
        }
    }
    grid_barrier();

    // ===== P5: reduce context partials (64 blocks); reset tick2 ===============
    if (bx == 0 && tid == 0) g_tick[2] = 0;
    if (gtid < B * E) {
        float s = 0.f;
#pragma unroll
        for (int pp = 0; pp < 16; pp++) s += g_ctxpart[pp * (B * E) + gtid];
        g_context[gtid] = s;
    }
    grid_barrier();

    // ===== P6 (tick 3): z-ctx partials; 512 tiles = kb(16 of k=64) x jt(32) ===
    for (;;) {
        __syncthreads();
        if (tid == 0) s_tile = atomicAdd(&g_tick[3], 1u);
        __syncthreads();
        const unsigned int tile = s_tile;
        if (tile >= 512u) break;
        const int kb = tile >> 5, jt = tile & 31;
        const int j = jt * 128 + (tid & 127);
        const int bh = tid >> 7;
        const int k0 = kb * 64;

        for (int idx = tid; idx < 32 * 64; idx += NT) {
            int b = idx >> 6, kk = idx & 63;
            pool[kk * 36 + b] = g_context[(size_t)b * E + k0 + kk];
        }
        __syncthreads();

        unsigned long long acc[4];
#pragma unroll
        for (int p = 0; p < 4; p++) acc[p] = 0ull;
        const float* wcol = Wk + (size_t)(DIN + k0) * G4 + j;
#pragma unroll 8
        for (int kk = 0; kk < 64; kk++) {
            float w = wcol[(size_t)kk * G4];
            unsigned long long ww = pack2(w, w);
            const unsigned long long* xp =
                reinterpret_cast<const unsigned long long*>(&pool[kk * 36]) + bh * 4;
#pragma unroll
            for (int p = 0; p < 4; p++) acc[p] = fma2(xp[p], ww, acc[p]);
        }
        float* outp = g_zpart + (size_t)(NSPL_IND + kb) * (B * G4);
#pragma unroll
        for (int p = 0; p < 4; p++) {
            float a, b2; unpack2(acc[p], a, b2);
            outp[(size_t)(bh * 8 + 2 * p) * G4 + j] = a;
            outp[(size_t)(bh * 8 + 2 * p + 1) * G4 + j] = b2;
        }
    }
    grid_barrier();

    // ===== P7: reduce z partials + bias, gates, outputs; reset tick3 ==========
    if (bx == 0 && tid == 0) g_tick[3] = 0;
    if (gtid < B * U) {
        const int b = gtid >> 10, u = gtid & (U - 1);
        float z[4];
#pragma unroll
        for (int g = 0; g < 4; g++) {
            int col = g * U + u;
            float s = bias[col];
            const float* zp = g_zpart + (size_t)b * G4 + col;
#pragma unroll
            for (int kb = 0; kb < NSPL; kb++)
                s += zp[(size_t)kb * (B * G4)];
            z[g] = s;
        }
        float c_new = sigmoid_acc(z[1]) * c[gtid] + sigmoid_acc(z[0]) * tanhf(z[2]);
        float h_new = sigmoid_acc(z[3]) * tanhf(c_new);
        out[gtid]             = h_new;  // lstmout
        out[B * U + gtid]     = h_new;  // h state
        out[2 * B * U + gtid] = c_new;  // c state
    }
}

// ---------------- launcher ------------------------------------------------------
extern "C" void kernel_launch(void* const* d_in, const int* in_sizes, int n_in,
                              void* d_out, int out_size) {
    const float* inputs      = (const float*)d_in[0];
    const float* h           = (const float*)d_in[1];
    const float* c           = (const float*)d_in[2];
    const float* speech_enc  = (const float*)d_in[3];
    const float* encodestate = (const float*)d_in[4];
    const float* Wa_w        = (const float*)d_in[5];
    const float* Wa_b        = (const float*)d_in[6];
    const float* va_w        = (const float*)d_in[7];
    const float* va_b        = (const float*)d_in[8];
    const float* kernel_w    = (const float*)d_in[9];
    const float* rec_kernel  = (const float*)d_in[10];
    const float* bias        = (const float*)d_in[11];
    float* out = (float*)d_out;

    mono_cell<<<GRID, NT>>>(inputs, h, c, speech_enc, encodestate,
                            Wa_w, Wa_b, va_w, va_b,
                            kernel_w, rec_kernel, bias, out);
}

// round 12
// speedup vs baseline: 1.0185x; 1.0185x over previous
#include <cuda_runtime.h>
#include <math.h>

#define B 32
#define T 512
#define U 1024
#define E 1024
#define DIN 256
#define G4 4096        // 4*U
#define NSPL_IND 10    // independent z chunks (2 inputs + 8 h), k=128 each
#define NSPL_CTX 16    // context z chunks, k=64 each
#define NSPL (NSPL_IND + NSPL_CTX)
#define NCTXP 32       // context partials (16 t each)
#define GRID 444       // 148 SMs x 3 resident blocks (regs<=42 via launch_bounds)
#define NT 512

// ---------------- scratch (device globals: no allocations allowed) ----------
__device__ float g_qpart[16 * B * U];
__device__ float g_query[B * U];
__device__ float g_logits[B * T];
__device__ float g_attn[B * T];
__device__ float g_ctxpart[NCTXP * B * E];
__device__ float g_context[B * E];
__device__ float g_zpart[NSPL * B * G4];
__device__ unsigned int g_count = 0;  // barrier counter (self-resets)
__device__ unsigned int g_gen = 0;    // barrier generation (monotonic)

// ---------------- helpers ----------------------------------------------------
__device__ __forceinline__ unsigned long long pack2(float a, float b) {
    unsigned long long r;
    asm("mov.b64 %0, {%1, %2};" : "=l"(r) : "r"(__float_as_uint(a)), "r"(__float_as_uint(b)));
    return r;
}
__device__ __forceinline__ void unpack2(unsigned long long v, float& a, float& b) {
    unsigned int lo, hi;
    asm("mov.b64 {%0, %1}, %2;" : "=r"(lo), "=r"(hi) : "l"(v));
    a = __uint_as_float(lo); b = __uint_as_float(hi);
}
__device__ __forceinline__ unsigned long long fma2(unsigned long long x,
                                                   unsigned long long y,
                                                   unsigned long long a) {
    unsigned long long d;
    asm("fma.rn.f32x2 %0, %1, %2, %3;" : "=l"(d) : "l"(x), "l"(y), "l"(a));
    return d;
}
__device__ __forceinline__ float tanh_hw(float x) {
    float y;
    asm("tanh.approx.f32 %0, %1;" : "=f"(y) : "f"(x));
    return y;
}
__device__ __forceinline__ float sigmoid_acc(float x) {
    return 1.0f / (1.0f + expf(-x));
}
__device__ __forceinline__ float4 ldcs4(const float4* p) {
    float4 v;
    asm("ld.global.cs.v4.f32 {%0,%1,%2,%3}, [%4];"
        : "=f"(v.x), "=f"(v.y), "=f"(v.z), "=f"(v.w) : "l"(p));
    return v;
}

// Grid-wide barrier: counter + monotonic generation (replay-safe).
__device__ __forceinline__ void grid_barrier() {
    __syncthreads();
    if (threadIdx.x == 0) {
        __threadfence();
        unsigned int gen = atomicAdd(&g_gen, 0u);
        unsigned int arrived = atomicAdd(&g_count, 1u) + 1u;
        if (arrived == GRID) {
            g_count = 0;
            __threadfence();
            atomicAdd(&g_gen, 1u);
        } else {
            while (atomicAdd(&g_gen, 0u) == gen) { __nanosleep(64); }
        }
        __threadfence();
    }
    __syncthreads();
}

// ---------------- the whole cell: static strided tiles, occ 3/SM --------------
__global__ void __launch_bounds__(NT, 3) mono_cell(
    const float* __restrict__ inputs, const float* __restrict__ h,
    const float* __restrict__ c, const float* __restrict__ se,
    const float* __restrict__ es, const float* __restrict__ Wa,
    const float* __restrict__ Wa_b, const float* __restrict__ va_w,
    const float* __restrict__ va_b, const float* __restrict__ Wk,
    const float* __restrict__ Wr, const float* __restrict__ bias,
    float* __restrict__ out)
{
    __shared__ __align__(16) float pool[128 * 36];   // 18.4KB, reused per phase
    const int tid = threadIdx.x;
    const int bx = blockIdx.x;
    const int gtid = bx * NT + tid;

    // ===== P1: 448 tiles = 128 query-partial + 320 independent-z ==============
    for (int tile = bx; tile < 448; tile += GRID) {
        if (tile < 128) {
            // query partial: ut(8 of j=128) x kb(16 of k=64); bh(4) covers 8 b
            const int ut = tile >> 4, kb = tile & 15;
            const int k0 = kb * 64;
            const int u = ut * 128 + (tid & 127);
            const int bh = tid >> 7;

            __syncthreads();
            for (int idx = tid; idx < 32 * 64; idx += NT) {
                int b = idx >> 6, k = idx & 63;
                pool[k * 36 + b] = h[b * U + k0 + k];
            }
            __syncthreads();

            unsigned long long acc[4];
#pragma unroll
            for (int p = 0; p < 4; p++) acc[p] = 0ull;
            const float* wcol = Wa + (size_t)k0 * U + u;
#pragma unroll 8
            for (int k = 0; k < 64; k++) {
                float w = wcol[(size_t)k * U];
                unsigned long long ww = pack2(w, w);
                const unsigned long long* xp =
                    reinterpret_cast<const unsigned long long*>(&pool[k * 36]) + bh * 4;
#pragma unroll
                for (int p = 0; p < 4; p++) acc[p] = fma2(xp[p], ww, acc[p]);
            }
            float* outp = g_qpart + (size_t)kb * (B * U);
#pragma unroll
            for (int p = 0; p < 4; p++) {
                float a, b2; unpack2(acc[p], a, b2);
                outp[(bh * 8 + 2 * p) * U + u] = a;
                outp[(bh * 8 + 2 * p + 1) * U + u] = b2;
            }
        } else {
            // independent z: kb(10 of k=128) x jt(32 of j=128)
            const int zi = tile - 128;
            const int kb = zi >> 5, jt = zi & 31;
            const int j = jt * 128 + (tid & 127);
            const int bh = tid >> 7;

            const float* xsrc; int x_ld, xk0;
            const float* W;    int wk0;
            if (kb < 2) { xsrc = inputs; x_ld = DIN; xk0 = kb * 128;       W = Wk; wk0 = kb * 128; }
            else        { xsrc = h;      x_ld = U;   xk0 = (kb - 2) * 128; W = Wr; wk0 = (kb - 2) * 128; }

            __syncthreads();
            for (int idx = tid; idx < 32 * 128; idx += NT) {
                int b = idx >> 7, kk = idx & 127;
                pool[kk * 36 + b] = xsrc[(size_t)b * x_ld + xk0 + kk];
            }
            __syncthreads();

            unsigned long long acc[4];
#pragma unroll
            for (int p = 0; p < 4; p++) acc[p] = 0ull;
            const float* wcol = W + (size_t)wk0 * G4 + j;
#pragma unroll 8
            for (int kk = 0; kk < 128; kk++) {
                float w = wcol[(size_t)kk * G4];
                unsigned long long ww = pack2(w, w);
                const unsigned long long* xp =
                    reinterpret_cast<const unsigned long long*>(&pool[kk * 36]) + bh * 4;
#pragma unroll
                for (int p = 0; p < 4; p++) acc[p] = fma2(xp[p], ww, acc[p]);
            }
            float* outp = g_zpart + (size_t)kb * (B * G4);
#pragma unroll
            for (int p = 0; p < 4; p++) {
                float a, b2; unpack2(acc[p], a, b2);
                outp[(size_t)(bh * 8 + 2 * p) * G4 + j] = a;
                outp[(size_t)(bh * 8 + 2 * p + 1) * G4 + j] = b2;
            }
        }
    }
    grid_barrier();

    // ===== P1b: reduce query partials + bias ==================================
    if (gtid < B * U) {
        float s = Wa_b[gtid & (U - 1)];
#pragma unroll
        for (int kb = 0; kb < 16; kb++) s += g_qpart[kb * (B * U) + gtid];
        g_query[gtid] = s;
    }
    grid_barrier();

    // ===== P2: scores; 1024 tiles = b(32) x sl(32 slices of 16 rows) ==========
    {
        // va cached once per block
        for (int i4 = tid; i4 < 256; i4 += NT)
            reinterpret_cast<float4*>(pool + 1024)[i4] =
                reinterpret_cast<const float4*>(va_w)[i4];
        int cur_b = -1;
        const float vb = va_b[0];
        const int lane = tid & 31;

        for (int tile = bx; tile < 1024; tile += GRID) {
            const int b = tile >> 5, sl = tile & 31;
            if (b != cur_b) {
                __syncthreads();
                for (int i4 = tid; i4 < 256; i4 += NT)
                    reinterpret_cast<float4*>(pool)[i4] =
                        reinterpret_cast<const float4*>(g_query + b * U)[i4];
                __syncthreads();
                cur_b = b;
            }
            const float4* qs = reinterpret_cast<const float4*>(pool);
            const float4* vs = reinterpret_cast<const float4*>(pool + 1024);
            const int r = sl * 16 + (tid >> 5);    // one row per warp
            const float4* erow = reinterpret_cast<const float4*>(es)
                               + (size_t)(b * T + r) * 256;
            float4 e[8];
#pragma unroll
            for (int i = 0; i < 8; i++) e[i] = ldcs4(&erow[lane + i * 32]);
            float s = 0.f;
#pragma unroll
            for (int i = 0; i < 8; i++) {
                int u4 = lane + i * 32;
                float4 q4 = qs[u4];
                float4 v4 = vs[u4];
                s += tanh_hw(q4.x + e[i].x) * v4.x;
                s += tanh_hw(q4.y + e[i].y) * v4.y;
                s += tanh_hw(q4.z + e[i].z) * v4.z;
                s += tanh_hw(q4.w + e[i].w) * v4.w;
            }
#pragma unroll
            for (int o = 16; o; o >>= 1) s += __shfl_xor_sync(0xffffffffu, s, o);
            if (lane == 0) g_logits[b * T + r] = s + vb;
        }
    }
    grid_barrier();

    // ===== P3: softmax per batch (32 blocks) ==================================
    if (bx < 32) {
        float* red = pool;
        const int b = bx;
        const int lane = tid & 31, wid = tid >> 5;

        float l = g_logits[b * T + tid];
        float m = l;
#pragma unroll
        for (int o = 16; o; o >>= 1) m = fmaxf(m, __shfl_xor_sync(0xffffffffu, m, o));
        if (lane == 0) red[wid] = m;
        __syncthreads();
        if (tid < 32) {
            float v = red[tid & 15];
#pragma unroll
            for (int o = 8; o; o >>= 1) v = fmaxf(v, __shfl_xor_sync(0xffffffffu, v, o));
            if (tid == 0) red[16] = v;
        }
        __syncthreads();
        float p = __expf(l - red[16]);
        float sum = p;
#pragma unroll
        for (int o = 16; o; o >>= 1) sum += __shfl_xor_sync(0xffffffffu, sum, o);
        if (lane == 0) red[wid] = sum;
        __syncthreads();
        if (tid < 32) {
            float v = (tid < 16) ? red[tid] : 0.f;
#pragma unroll
            for (int o = 8; o; o >>= 1) v += __shfl_xor_sync(0xffffffffu, v, o);
            if (tid == 0) red[17] = v;
        }
        __syncthreads();
        g_attn[b * T + tid] = p / red[17];
    }
    grid_barrier();

    // ===== P4: context partials; 512 tiles = b(32) x tc(16 chunks of 32 t) ====
    for (int tile = bx; tile < 512; tile += GRID) {
        const int b = tile >> 4, tc = tile & 15;
        const int t0 = tc * 32;

        __syncthreads();
        if (tid < 32) pool[tid] = g_attn[b * T + t0 + tid];
        __syncthreads();

        const int tsub = tid >> 8;            // 2 sub-chunks of 16 t
        const int e4 = tid & 255;             // full E as 256 float4
        const float* ap = pool + tsub * 16;
        const float4* se4 = reinterpret_cast<const float4*>(se)
                          + ((size_t)(b * T + t0 + tsub * 16)) * 256 + e4;
        float4 acc = make_float4(0.f, 0.f, 0.f, 0.f);
#pragma unroll
        for (int i = 0; i < 16; i++) {
            float pw = ap[i];
            float4 v = ldcs4(&se4[(size_t)i * 256]);
            acc.x += pw * v.x; acc.y += pw * v.y; acc.z += pw * v.z; acc.w += pw * v.w;
        }
        const int pp = tc * 2 + tsub;         // 32 partials
        reinterpret_cast<float4*>(g_ctxpart)[(size_t)(pp * B + b) * 256 + e4] = acc;
    }
    grid_barrier();

    // ===== P5: reduce context partials ========================================
    if (gtid < B * E) {
        float s = 0.f;
#pragma unroll
        for (int pp = 0; pp < NCTXP; pp++) s += g_ctxpart[pp * (B * E) + gtid];
        g_context[gtid] = s;
    }
    grid_barrier();

    // ===== P6: z-ctx partials; 512 tiles = kb(16 of k=64) x jt(32 of j=128) ===
    for (int tile = bx; tile < 512; tile += GRID) {
        const int kb = tile >> 5, jt = tile & 31;
        const int j = jt * 128 + (tid & 127);
        const int bh = tid >> 7;
        const int k0 = kb * 64;

        __syncthreads();
        for (int idx = tid; idx < 32 * 64; idx += NT) {
            int b = idx >> 6, kk = idx & 63;
            pool[kk * 36 + b] = g_context[(size_t)b * E + k0 + kk];
        }
        __syncthreads();

        unsigned long long acc[4];
#pragma unroll
        for (int p = 0; p < 4; p++) acc[p] = 0ull;
        const float* wcol = Wk + (size_t)(DIN + k0) * G4 + j;
#pragma unroll 8
        for (int kk = 0; kk < 64; kk++) {
            float w = wcol[(size_t)kk * G4];
            unsigned long long ww = pack2(w, w);
            const unsigned long long* xp =
                reinterpret_cast<const unsigned long long*>(&pool[kk * 36]) + bh * 4;
#pragma unroll
            for (int p = 0; p < 4; p++) acc[p] = fma2(xp[p], ww, acc[p]);
        }
        float* outp = g_zpart + (size_t)(NSPL_IND + kb) * (B * G4);
#pragma unroll
        for (int p = 0; p < 4; p++) {
            float a, b2; unpack2(acc[p], a, b2);
            outp[(size_t)(bh * 8 + 2 * p) * G4 + j] = a;
            outp[(size_t)(bh * 8 + 2 * p + 1) * G4 + j] = b2;
        }
    }
    grid_barrier();

    // ===== P7: reduce z partials + bias, gates, outputs =======================
    if (gtid < B * U) {
        const int b = gtid >> 10, u = gtid & (U - 1);
        float z[4];
#pragma unroll
        for (int g = 0; g < 4; g++) {
            int col = g * U + u;
            float s = bias[col];
            const float* zp = g_zpart + (size_t)b * G4 + col;
#pragma unroll
            for (int kb = 0; kb < NSPL; kb++)
                s += zp[(size_t)kb * (B * G4)];
            z[g] = s;
        }
        float c_new = sigmoid_acc(z[1]) * c[gtid] + sigmoid_acc(z[0]) * tanhf(z[2]);
        float h_new = sigmoid_acc(z[3]) * tanhf(c_new);
        out[gtid]             = h_new;  // lstmout
        out[B * U + gtid]     = h_new;  // h state
        out[2 * B * U + gtid] = c_new;  // c state
    }
}

// ---------------- launcher ------------------------------------------------------
extern "C" void kernel_launch(void* const* d_in, const int* in_sizes, int n_in,
                              void* d_out, int out_size) {
    const float* inputs      = (const float*)d_in[0];
    const float* h           = (const float*)d_in[1];
    const float* c           = (const float*)d_in[2];
    const float* speech_enc  = (const float*)d_in[3];
    const float* encodestate = (const float*)d_in[4];
    const float* Wa_w        = (const float*)d_in[5];
    const float* Wa_b        = (const float*)d_in[6];
    const float* va_w        = (const float*)d_in[7];
    const float* va_b        = (const float*)d_in[8];
    const float* kernel_w    = (const float*)d_in[9];
    const float* rec_kernel  = (const float*)d_in[10];
    const float* bias        = (const float*)d_in[11];
    float* out = (float*)d_out;

    mono_cell<<<GRID, NT>>>(inputs, h, c, speech_enc, encodestate,
                            Wa_w, Wa_b, va_w, va_b,
                            kernel_w, rec_kernel, bias, out);
}

// round 13
// speedup vs baseline: 1.1586x; 1.1375x over previous
#include <cuda_runtime.h>
#include <math.h>

#define B 32
#define T 512
#define U 1024
#define E 1024
#define DIN 256
#define G4 4096        // 4*U
#define NSPL_IND 10    // independent z chunks (2 inputs + 8 h), k=128 each
#define NSPL_CTX 16    // context z chunks, k=64 each
#define NSPL (NSPL_IND + NSPL_CTX)
#define NCTXP 32       // context partials (one per 16-t slice)
#define GRID 296       // 148 SMs x 2 resident blocks
#define NT 512

// ---------------- scratch (device globals: no allocations allowed) ----------
__device__ float g_qpart[16 * B * U];
__device__ float g_query[B * U];
__device__ float g_tsum[B * NCTXP];        // per-slice exp sums (deterministic)
__device__ float g_ctxpart[NCTXP * B * E]; // unnormalized context partials
__device__ float g_context[B * E];
__device__ float g_zpart[NSPL * B * G4];
__device__ unsigned int g_count = 0;  // barrier counter (self-resets)
__device__ unsigned int g_gen = 0;    // barrier generation (monotonic)

// ---------------- helpers ----------------------------------------------------
__device__ __forceinline__ unsigned long long pack2(float a, float b) {
    unsigned long long r;
    asm("mov.b64 %0, {%1, %2};" : "=l"(r) : "r"(__float_as_uint(a)), "r"(__float_as_uint(b)));
    return r;
}
__device__ __forceinline__ void unpack2(unsigned long long v, float& a, float& b) {
    unsigned int lo, hi;
    asm("mov.b64 {%0, %1}, %2;" : "=r"(lo), "=r"(hi) : "l"(v));
    a = __uint_as_float(lo); b = __uint_as_float(hi);
}
__device__ __forceinline__ unsigned long long fma2(unsigned long long x,
                                                   unsigned long long y,
                                                   unsigned long long a) {
    unsigned long long d;
    asm("fma.rn.f32x2 %0, %1, %2, %3;" : "=l"(d) : "l"(x), "l"(y), "l"(a));
    return d;
}
__device__ __forceinline__ float tanh_hw(float x) {
    float y;
    asm("tanh.approx.f32 %0, %1;" : "=f"(y) : "f"(x));
    return y;
}
__device__ __forceinline__ float sigmoid_acc(float x) {
    return 1.0f / (1.0f + expf(-x));
}
__device__ __forceinline__ float4 ldcs4(const float4* p) {
    float4 v;
    asm("ld.global.cs.v4.f32 {%0,%1,%2,%3}, [%4];"
        : "=f"(v.x), "=f"(v.y), "=f"(v.z), "=f"(v.w) : "l"(p));
    return v;
}

// Grid-wide barrier: counter + monotonic generation (replay-safe).
__device__ __forceinline__ void grid_barrier() {
    __syncthreads();
    if (threadIdx.x == 0) {
        __threadfence();
        unsigned int gen = atomicAdd(&g_gen, 0u);
        unsigned int arrived = atomicAdd(&g_count, 1u) + 1u;
        if (arrived == GRID) {
            g_count = 0;
            __threadfence();
            atomicAdd(&g_gen, 1u);
        } else {
            while (atomicAdd(&g_gen, 0u) == gen) { __nanosleep(64); }
        }
        __threadfence();
    }
    __syncthreads();
}

// ---------------- the whole cell: fused attention stream, 5 barriers ----------
__global__ void __launch_bounds__(NT, 2) mono_cell(
    const float* __restrict__ inputs, const float* __restrict__ h,
    const float* __restrict__ c, const float* __restrict__ se,
    const float* __restrict__ es, const float* __restrict__ Wa,
    const float* __restrict__ Wa_b, const float* __restrict__ va_w,
    const float* __restrict__ va_b, const float* __restrict__ Wk,
    const float* __restrict__ Wr, const float* __restrict__ bias,
    float* __restrict__ out)
{
    __shared__ __align__(16) float pool[128 * 36];   // 18.4KB, reused per phase
    const int tid = threadIdx.x;
    const int bx = blockIdx.x;
    const int gtid = bx * NT + tid;

    // ===== P1: query partials (64 blk) + independent z partials (160 blk) =====
    if (bx < 64) {
        const int tile = bx >> 4, kb = bx & 15;
        const int k0 = kb * 64;
        const int u = tile * 256 + (tid & 255);
        const int bh = tid >> 8;

        for (int idx = tid; idx < 32 * 64; idx += NT) {
            int b = idx >> 6, k = idx & 63;
            pool[k * 36 + b] = h[b * U + k0 + k];
        }
        __syncthreads();

        unsigned long long acc[8];
#pragma unroll
        for (int p = 0; p < 8; p++) acc[p] = 0ull;
        const float* wcol = Wa + (size_t)k0 * U + u;
#pragma unroll 8
        for (int k = 0; k < 64; k++) {
            float w = wcol[(size_t)k * U];
            unsigned long long ww = pack2(w, w);
            const unsigned long long* xp =
                reinterpret_cast<const unsigned long long*>(&pool[k * 36]) + bh * 8;
#pragma unroll
            for (int p = 0; p < 8; p++) acc[p] = fma2(xp[p], ww, acc[p]);
        }
        float* outp = g_qpart + (size_t)kb * (B * U);
#pragma unroll
        for (int p = 0; p < 8; p++) {
            float a, b2; unpack2(acc[p], a, b2);
            outp[(bh * 16 + 2 * p) * U + u] = a;
            outp[(bh * 16 + 2 * p + 1) * U + u] = b2;
        }
    } else if (bx < 64 + 160) {
        const int zi = bx - 64;
        const int kb = zi >> 4, jt = zi & 15;
        const int j = jt * 256 + (tid & 255);
        const int bh = tid >> 8;

        const float* xsrc; int x_ld, xk0;
        const float* W;    int wk0;
        if (kb < 2) { xsrc = inputs; x_ld = DIN; xk0 = kb * 128;       W = Wk; wk0 = kb * 128; }
        else        { xsrc = h;      x_ld = U;   xk0 = (kb - 2) * 128; W = Wr; wk0 = (kb - 2) * 128; }

        for (int idx = tid; idx < 32 * 128; idx += NT) {
            int b = idx >> 7, kk = idx & 127;
            pool[kk * 36 + b] = xsrc[(size_t)b * x_ld + xk0 + kk];
        }
        __syncthreads();

        unsigned long long acc[8];
#pragma unroll
        for (int p = 0; p < 8; p++) acc[p] = 0ull;
        const float* wcol = W + (size_t)wk0 * G4 + j;
#pragma unroll 8
        for (int kk = 0; kk < 128; kk++) {
            float w = wcol[(size_t)kk * G4];
            unsigned long long ww = pack2(w, w);
            const unsigned long long* xp =
                reinterpret_cast<const unsigned long long*>(&pool[kk * 36]) + bh * 8;
#pragma unroll
            for (int p = 0; p < 8; p++) acc[p] = fma2(xp[p], ww, acc[p]);
        }
        float* outp = g_zpart + (size_t)kb * (B * G4);
#pragma unroll
        for (int p = 0; p < 8; p++) {
            float a, b2; unpack2(acc[p], a, b2);
            outp[(size_t)(bh * 16 + 2 * p) * G4 + j] = a;
            outp[(size_t)(bh * 16 + 2 * p + 1) * G4 + j] = b2;
        }
    }
    grid_barrier();

    // ===== P1b: reduce query partials + bias ==================================
    if (gtid < B * U) {
        float s = Wa_b[gtid & (U - 1)];
#pragma unroll
        for (int kb = 0; kb < 16; kb++) s += g_qpart[kb * (B * U) + gtid];
        g_query[gtid] = s;
    }
    grid_barrier();

    // ===== P24 fused: scores -> exp -> context partial, one streaming phase ===
    // 1024 tiles = b(32) x sl(32 slices of 16 t). No softmax barrier: context
    // accumulates exp(l)-weighted (unnormalized); per-slice sums -> g_tsum.
    {
        // pool layout (floats): q[0,1024) va[1024,2048) accum[2048,4096) ps[4096,4112)
        float4* qs4 = reinterpret_cast<float4*>(pool);
        float4* vs4 = reinterpret_cast<float4*>(pool + 1024);
        float4* ac4 = reinterpret_cast<float4*>(pool + 2048);
        float* ps = pool + 4096;
        const float vb = va_b[0];
        const int w = tid >> 5, lane = tid & 31;

        for (int tile = bx; tile < B * NCTXP; tile += GRID) {
            const int b = tile >> 5, sl = tile & 31;
            const int t0 = sl * 16;

            __syncthreads();   // pool reuse fence
            for (int i4 = tid; i4 < 256; i4 += NT) {
                qs4[i4] = reinterpret_cast<const float4*>(g_query + b * U)[i4];
                vs4[i4] = reinterpret_cast<const float4*>(va_w)[i4];
            }
            __syncthreads();

            // --- 16 logits (one row per warp), exp in smem ---
            {
                const float4* erow = reinterpret_cast<const float4*>(es)
                                   + (size_t)(b * T + t0 + w) * 256;
                float4 e[8];
#pragma unroll
                for (int i = 0; i < 8; i++) e[i] = ldcs4(&erow[lane + i * 32]);
                float s = 0.f;
#pragma unroll
                for (int i = 0; i < 8; i++) {
                    int u4 = lane + i * 32;
                    float4 q4 = qs4[u4];
                    float4 v4 = vs4[u4];
                    s += tanh_hw(q4.x + e[i].x) * v4.x;
                    s += tanh_hw(q4.y + e[i].y) * v4.y;
                    s += tanh_hw(q4.z + e[i].z) * v4.z;
                    s += tanh_hw(q4.w + e[i].w) * v4.w;
                }
#pragma unroll
                for (int o = 16; o; o >>= 1) s += __shfl_xor_sync(0xffffffffu, s, o);
                if (lane == 0) ps[w] = __expf(s + vb);   // logits are O(1): safe
            }
            __syncthreads();

            if (tid == 0) {
                float ts = 0.f;
#pragma unroll
                for (int i = 0; i < 16; i++) ts += ps[i];
                g_tsum[b * NCTXP + sl] = ts;             // deterministic order
            }

            // --- context partial over these 16 t-rows ---
            const int tsub = tid >> 8;                   // 2 halves of 8 t
            const int e4 = tid & 255;
            const float* ap = ps + tsub * 8;
            const float4* se4 = reinterpret_cast<const float4*>(se)
                              + ((size_t)(b * T + t0 + tsub * 8)) * 256 + e4;
            float4 acc = make_float4(0.f, 0.f, 0.f, 0.f);
#pragma unroll
            for (int i = 0; i < 8; i++) {
                float pw = ap[i];
                float4 v = ldcs4(&se4[(size_t)i * 256]);
                acc.x += pw * v.x; acc.y += pw * v.y;
                acc.z += pw * v.z; acc.w += pw * v.w;
            }
            ac4[tsub * 256 + e4] = acc;
            __syncthreads();
            if (tid < 256) {
                float4 r0 = ac4[tid], r1 = ac4[256 + tid];
                float4 r;
                r.x = r0.x + r1.x; r.y = r0.y + r1.y;
                r.z = r0.z + r1.z; r.w = r0.w + r1.w;
                reinterpret_cast<float4*>(g_ctxpart)[(size_t)(sl * B + b) * 256 + tid] = r;
            }
        }
    }
    grid_barrier();

    // ===== P5: reduce context partials + normalize by esum ====================
    if (bx < 64) {
        const int b = bx >> 1;
        const int eoff = (bx & 1) * 512;
        if (tid < NCTXP) pool[tid] = g_tsum[b * NCTXP + tid];
        __syncthreads();
        if (tid == 0) {
            float s = 0.f;
#pragma unroll
            for (int i = 0; i < NCTXP; i++) s += pool[i];
            pool[NCTXP] = 1.0f / s;
        }
        __syncthreads();
        const float inv = pool[NCTXP];
        const int e = eoff + tid;
        float s = 0.f;
#pragma unroll
        for (int pp = 0; pp < NCTXP; pp++) s += g_ctxpart[(size_t)(pp * B + b) * E + e];
        g_context[b * E + e] = s * inv;
    }
    grid_barrier();

    // ===== P6: z-ctx partials (256 blocks, stage from normalized g_context) ===
    if (bx < 256) {
        const int kb = bx >> 4, jt = bx & 15;
        const int j = jt * 256 + (tid & 255);
        const int bh = tid >> 8;
        const int k0 = kb * 64;

        for (int idx = tid; idx < 32 * 64; idx += NT) {
            int b = idx >> 6, kk = idx & 63;
            pool[kk * 36 + b] = g_context[(size_t)b * E + k0 + kk];
        }
        __syncthreads();

        unsigned long long acc[8];
#pragma unroll
        for (int p = 0; p < 8; p++) acc[p] = 0ull;
        const float* wcol = Wk + (size_t)(DIN + k0) * G4 + j;
#pragma unroll 8
        for (int kk = 0; kk < 64; kk++) {
            float w = wcol[(size_t)kk * G4];
            unsigned long long ww = pack2(w, w);
            const unsigned long long* xp =
                reinterpret_cast<const unsigned long long*>(&pool[kk * 36]) + bh * 8;
#pragma unroll
            for (int p = 0; p < 8; p++) acc[p] = fma2(xp[p], ww, acc[p]);
        }
        float* outp = g_zpart + (size_t)(NSPL_IND + kb) * (B * G4);
#pragma unroll
        for (int p = 0; p < 8; p++) {
            float a, b2; unpack2(acc[p], a, b2);
            outp[(size_t)(bh * 16 + 2 * p) * G4 + j] = a;
            outp[(size_t)(bh * 16 + 2 * p + 1) * G4 + j] = b2;
        }
    }
    grid_barrier();

    // ===== P7: reduce z partials + bias, gates, outputs =======================
    if (gtid < B * U) {
        const int b = gtid >> 10, u = gtid & (U - 1);
        float z[4];
#pragma unroll
        for (int g = 0; g < 4; g++) {
            int col = g * U + u;
            float s = bias[col];
            const float* zp = g_zpart + (size_t)b * G4 + col;
#pragma unroll
            for (int kb = 0; kb < NSPL; kb++)
                s += zp[(size_t)kb * (B * G4)];
            z[g] = s;
        }
        float c_new = sigmoid_acc(z[1]) * c[gtid] + sigmoid_acc(z[0]) * tanhf(z[2]);
        float h_new = sigmoid_acc(z[3]) * tanhf(c_new);
        out[gtid]             = h_new;  // lstmout
        out[B * U + gtid]     = h_new;  // h state
        out[2 * B * U + gtid] = c_new;  // c state
    }
}

// ---------------- launcher ------------------------------------------------------
extern "C" void kernel_launch(void* const* d_in, const int* in_sizes, int n_in,
                              void* d_out, int out_size) {
    const float* inputs      = (const float*)d_in[0];
    const float* h           = (const float*)d_in[1];
    const float* c           = (const float*)d_in[2];
    const float* speech_enc  = (const float*)d_in[3];
    const float* encodestate = (const float*)d_in[4];
    const float* Wa_w        = (const float*)d_in[5];
    const float* Wa_b        = (const float*)d_in[6];
    const float* va_w        = (const float*)d_in[7];
    const float* va_b        = (const float*)d_in[8];
    const float* kernel_w    = (const float*)d_in[9];
    const float* rec_kernel  = (const float*)d_in[10];
    const float* bias        = (const float*)d_in[11];
    float* out = (float*)d_out;

    mono_cell<<<GRID, NT>>>(inputs, h, c, speech_enc, encodestate,
                            Wa_w, Wa_b, va_w, va_b,
                            kernel_w, rec_kernel, bias, out);
}